// round 12
// baseline (speedup 1.0000x reference)
#include <cuda_runtime.h>
#include <cuda_bf16.h>
#include <cstdint>

#define TT   2048
#define DD   64
#define CH   64
#define NC   (TT/CH)    // 32 chunks
#define BH   64         // B*H
#define PIT  72         // smem pitch in bf16 elements (144B rows, ldmatrix conflict-free)
#define TILE_B (DD*PIT*2)  // 9216 bytes per 64x64 bf16 tile

// Inter-kernel state as bf16 hi/lo planes, packed 2 elems per u32.
// kv -> raw chunk states; prefix rewrites them in place-style into prefix planes.
__device__ uint32_t g_kh[(size_t)BH * NC * DD * DD / 2];  // 16 MB
__device__ uint32_t g_kl[(size_t)BH * NC * DD * DD / 2];
__device__ uint32_t g_sh[(size_t)BH * NC * DD * DD / 2];  // exclusive-prefix planes
__device__ uint32_t g_sl[(size_t)BH * NC * DD * DD / 2];

// ---------------------------------------------------------------------------
// helpers
// ---------------------------------------------------------------------------
__device__ __forceinline__ uint32_t smem_u32(const void* p) {
    uint32_t a;
    asm("{ .reg .u64 t; cvta.to.shared.u64 t, %1; cvt.u32.u64 %0, t; }" : "=r"(a) : "l"(p));
    return a;
}
__device__ __forceinline__ void ldsm4(uint32_t addr, uint32_t r[4]) {
    asm volatile("ldmatrix.sync.aligned.m8n8.x4.shared.b16 {%0,%1,%2,%3}, [%4];"
                 : "=r"(r[0]), "=r"(r[1]), "=r"(r[2]), "=r"(r[3]) : "r"(addr));
}
__device__ __forceinline__ void ldsm4t(uint32_t addr, uint32_t r[4]) {
    asm volatile("ldmatrix.sync.aligned.m8n8.x4.trans.shared.b16 {%0,%1,%2,%3}, [%4];"
                 : "=r"(r[0]), "=r"(r[1]), "=r"(r[2]), "=r"(r[3]) : "r"(addr));
}
__device__ __forceinline__ void mma16816(float c[4], const uint32_t a[4], uint32_t b0, uint32_t b1) {
    asm volatile(
        "mma.sync.aligned.m16n8k16.row.col.f32.bf16.bf16.f32 "
        "{%0,%1,%2,%3}, {%4,%5,%6,%7}, {%8,%9}, {%0,%1,%2,%3};"
        : "+f"(c[0]), "+f"(c[1]), "+f"(c[2]), "+f"(c[3])
        : "r"(a[0]), "r"(a[1]), "r"(a[2]), "r"(a[3]), "r"(b0), "r"(b1));
}
// packed: d = {hi lane: bf16(hi), lo lane: bf16(lo)}
__device__ __forceinline__ uint32_t cvt_bf2(float hi, float lo) {
    uint32_t d;
    asm("cvt.rn.bf16x2.f32 %0, %1, %2;" : "=r"(d) : "f"(hi), "f"(lo));
    return d;
}
// split pair (x -> lo lane, y -> hi lane) into hi-plane and lo-plane words
__device__ __forceinline__ void split2(float x, float y, uint32_t& h, uint32_t& l) {
    h = cvt_bf2(y, x);
    float rx = x - __uint_as_float(h << 16);
    float ry = y - __uint_as_float(h & 0xFFFF0000u);
    l = cvt_bf2(ry, rx);
}
__device__ __forceinline__ void split4(float4 f, uint2& hi, uint2& lo) {
    split2(f.x, f.y, hi.x, lo.x);
    split2(f.z, f.w, hi.y, lo.y);
}
// reconstruct packed pair to floats: x from lo lane, y from hi lane (exact)
__device__ __forceinline__ void recon2(uint32_t h, uint32_t l, float& x, float& y) {
    x = __uint_as_float(h << 16)          + __uint_as_float(l << 16);
    y = __uint_as_float(h & 0xFFFF0000u)  + __uint_as_float(l & 0xFFFF0000u);
}

// ---------------------------------------------------------------------------
// Kernel 1: KV_c = K_c^T V_c (R4 structure; writes split planes directly)
// ---------------------------------------------------------------------------
#define K1_KH 0
#define K1_KL (1*TILE_B)
#define K1_VH (2*TILE_B)
#define K1_VL (3*TILE_B)
#define K1_SMEM (4*TILE_B)

__global__ __launch_bounds__(128) void kv_kernel(const float* __restrict__ kg,
                                                 const float* __restrict__ vg) {
    extern __shared__ char sm[];
    const uint32_t sb = smem_u32(sm);
    const int tid = threadIdx.x, w = tid >> 5, l = tid & 31;
    const int c = blockIdx.x, bh = blockIdx.y;

    const float* kp = kg + ((size_t)bh * TT + (size_t)c * CH) * DD;
    const float* vp = vg + ((size_t)bh * TT + (size_t)c * CH) * DD;

#pragma unroll
    for (int it = 0; it < 8; it++) {
        int idx = tid + it * 128;
        int j = idx >> 4, d0 = (idx & 15) * 4;
        uint2 hi, lo;
        split4(*(const float4*)(kp + (size_t)j * DD + d0), hi, lo);
        *(uint2*)(sm + K1_KH + (j * PIT + d0) * 2) = hi;
        *(uint2*)(sm + K1_KL + (j * PIT + d0) * 2) = lo;
        split4(*(const float4*)(vp + (size_t)j * DD + d0), hi, lo);
        *(uint2*)(sm + K1_VH + (j * PIT + d0) * 2) = hi;
        *(uint2*)(sm + K1_VL + (j * PIT + d0) * 2) = lo;
    }
    __syncthreads();

    const int m0 = (w & 1) * 32, n0 = (w >> 1) * 32;
    const uint32_t aOff = (((l & 7) + ((l >> 4) & 1) * 8) * PIT + m0 + (l & 8)) * 2;
    const uint32_t bOff = (((l & 7) + (l & 8)) * PIT + n0 + ((l >> 4) & 1) * 8) * 2;

    float acc[2][4][4] = {};
    const uint32_t aSel[3] = {K1_KH, K1_KH, K1_KL};
    const uint32_t bSel[3] = {K1_VH, K1_VL, K1_VH};
#pragma unroll
    for (int p = 0; p < 3; p++) {
        const uint32_t aB = sb + aSel[p] + aOff, bB = sb + bSel[p] + bOff;
#pragma unroll
        for (int ks = 0; ks < 4; ks++) {
            const uint32_t ko = ks * 16 * PIT * 2;
            uint32_t a0[4], a1[4], b0[4], b1[4];
            ldsm4t(aB + ko, a0);
            ldsm4t(aB + ko + 32, a1);
            ldsm4t(bB + ko, b0);
            ldsm4t(bB + ko + 32, b1);
            mma16816(acc[0][0], a0, b0[0], b0[1]); mma16816(acc[0][1], a0, b0[2], b0[3]);
            mma16816(acc[0][2], a0, b1[0], b1[1]); mma16816(acc[0][3], a0, b1[2], b1[3]);
            mma16816(acc[1][0], a1, b0[0], b0[1]); mma16816(acc[1][1], a1, b0[2], b0[3]);
            mma16816(acc[1][2], a1, b1[0], b1[1]); mma16816(acc[1][3], a1, b1[2], b1[3]);
        }
    }

    // write split planes: one u32 per plane per (d, e-pair)
    uint32_t* oh = g_kh + ((size_t)(bh * NC + c)) * (DD * DD / 2);
    uint32_t* ol = g_kl + ((size_t)(bh * NC + c)) * (DD * DD / 2);
#pragma unroll
    for (int mi = 0; mi < 2; mi++)
#pragma unroll
        for (int ni = 0; ni < 4; ni++)
#pragma unroll
            for (int half = 0; half < 2; half++) {
                int d = m0 + mi * 16 + (l >> 2) + half * 8;
                int e2 = (n0 + ni * 8 + 2 * (l & 3)) >> 1;
                uint32_t h, lo;
                split2(acc[mi][ni][2 * half], acc[mi][ni][2 * half + 1], h, lo);
                oh[(size_t)d * (DD / 2) + e2] = h;
                ol[(size_t)d * (DD / 2) + e2] = lo;
            }
}

// ---------------------------------------------------------------------------
// Kernel 2: exclusive prefix over planes — batched loads, fp32 scan, plane out.
// ---------------------------------------------------------------------------
__global__ __launch_bounds__(256) void prefix_kernel() {
    const int e2 = blockIdx.x * 256 + threadIdx.x;   // pair index 0..2047
    const int bh = blockIdx.y;
    const size_t str = DD * DD / 2;
    const uint32_t* ih = g_kh + (size_t)bh * NC * str + e2;
    const uint32_t* il = g_kl + (size_t)bh * NC * str + e2;
    uint32_t* oh = g_sh + (size_t)bh * NC * str + e2;
    uint32_t* ol = g_sl + (size_t)bh * NC * str + e2;

    uint32_t vh[NC], vl[NC];
#pragma unroll
    for (int c = 0; c < NC; c++) {
        vh[c] = ih[(size_t)c * str];
        vl[c] = il[(size_t)c * str];
    }

    float rx = 0.f, ry = 0.f;
#pragma unroll
    for (int c = 0; c < NC; c++) {
        uint32_t h, lo;
        split2(rx, ry, h, lo);
        oh[(size_t)c * str] = h;
        ol[(size_t)c * str] = lo;
        float tx, ty;
        recon2(vh[c], vl[c], tx, ty);
        rx += tx;
        ry += ty;
    }
}

// ---------------------------------------------------------------------------
// Kernel 3 (R4 structure): P = tril(Q K^T); O = Q S + P V. S staged by copy.
// ---------------------------------------------------------------------------
#define K3_QH 0
#define K3_QL (1*TILE_B)
#define K3_KH (2*TILE_B)
#define K3_KL (3*TILE_B)
#define K3_VH (4*TILE_B)
#define K3_VL (5*TILE_B)
#define K3_SH (6*TILE_B)
#define K3_SL (7*TILE_B)
#define K3_SMEM (8*TILE_B)

__global__ __launch_bounds__(128) void out_kernel(const float* __restrict__ qg,
                                                  const float* __restrict__ kg,
                                                  const float* __restrict__ vg,
                                                  float* __restrict__ og) {
    extern __shared__ char sm[];
    const uint32_t sb = smem_u32(sm);
    const int tid = threadIdx.x, w = tid >> 5, l = tid & 31;
    const int c = blockIdx.x, bh = blockIdx.y;

    const float* qp = qg + ((size_t)bh * TT + (size_t)c * CH) * DD;
    const float* kp = kg + ((size_t)bh * TT + (size_t)c * CH) * DD;
    const float* vp = vg + ((size_t)bh * TT + (size_t)c * CH) * DD;
    const uint32_t* sph = g_sh + ((size_t)(bh * NC + c)) * (DD * DD / 2);
    const uint32_t* spl = g_sl + ((size_t)(bh * NC + c)) * (DD * DD / 2);

#pragma unroll
    for (int it = 0; it < 8; it++) {
        int idx = tid + it * 128;
        int r = idx >> 4, d0 = (idx & 15) * 4;
        const uint32_t so = (r * PIT + d0) * 2;
        uint2 hi, lo;
        split4(*(const float4*)(qp + (size_t)r * DD + d0), hi, lo);
        *(uint2*)(sm + K3_QH + so) = hi;  *(uint2*)(sm + K3_QL + so) = lo;
        split4(*(const float4*)(kp + (size_t)r * DD + d0), hi, lo);
        *(uint2*)(sm + K3_KH + so) = hi;  *(uint2*)(sm + K3_KL + so) = lo;
        split4(*(const float4*)(vp + (size_t)r * DD + d0), hi, lo);
        *(uint2*)(sm + K3_VH + so) = hi;  *(uint2*)(sm + K3_VL + so) = lo;
        // S: bare plane copy
        const size_t si = ((size_t)r * DD + d0) / 2;
        *(uint2*)(sm + K3_SH + so) = *(const uint2*)(sph + si);
        *(uint2*)(sm + K3_SL + so) = *(const uint2*)(spl + si);
    }
    __syncthreads();

    const int m0 = w * 16;
    const int gid = l >> 2, tig = l & 3;
    const int i0 = m0 + gid;
    const uint32_t aOffN = ((m0 + (l & 15)) * PIT + ((l >> 4) << 3)) * 2;
    const uint32_t bOffN = (((l & 7) + ((l & 16) >> 1)) * PIT + ((l >> 3) & 1) * 8) * 2;
    const uint32_t bOffT = (((l & 7) + (l & 8)) * PIT + ((l >> 4) & 1) * 8) * 2;

    // ---- P = Q K^T (causal: only n-blocks j <= 16(w+1)) ----
    float accP[8][4] = {};
    {
        const uint32_t aS[3] = {K3_QH, K3_QH, K3_QL};
        const uint32_t bS[3] = {K3_KH, K3_KL, K3_KH};
#pragma unroll
        for (int p = 0; p < 3; p++) {
            const uint32_t aB = sb + aS[p] + aOffN, bB = sb + bS[p] + bOffN;
#pragma unroll
            for (int ks = 0; ks < 4; ks++) {
                uint32_t a[4];
                ldsm4(aB + ks * 32, a);
#pragma unroll
                for (int nb = 0; nb < 4; nb++)
                    if (nb <= w) {
                        uint32_t b[4];
                        ldsm4(bB + nb * 16 * PIT * 2 + ks * 32, b);
                        mma16816(accP[2 * nb],     a, b[0], b[1]);
                        mma16816(accP[2 * nb + 1], a, b[2], b[3]);
                    }
            }
        }
    }

    // ---- mask + in-register split to A-operand fragments ----
    uint32_t aPh[4][4], aPl[4][4];
#pragma unroll
    for (int nb = 0; nb < 4; nb++)
        if (nb <= w) {
#pragma unroll
            for (int s2 = 0; s2 < 2; s2++) {
                const int j0 = 16 * nb + 8 * s2 + 2 * tig;
                float c0 = (j0     <= i0)     ? accP[2 * nb + s2][0] : 0.f;
                float c1 = (j0 + 1 <= i0)     ? accP[2 * nb + s2][1] : 0.f;
                float c2 = (j0     <= i0 + 8) ? accP[2 * nb + s2][2] : 0.f;
                float c3 = (j0 + 1 <= i0 + 8) ? accP[2 * nb + s2][3] : 0.f;
                split2(c0, c1, aPh[nb][2 * s2],     aPl[nb][2 * s2]);
                split2(c2, c3, aPh[nb][2 * s2 + 1], aPl[nb][2 * s2 + 1]);
            }
        }

    // ---- O1 = Q @ S (B = S^T via trans loads of S[d][e]) ----
    float accO[8][4] = {};
    {
        const uint32_t aS[3] = {K3_QH, K3_QH, K3_QL};
        const uint32_t bS[3] = {K3_SH, K3_SL, K3_SH};
#pragma unroll
        for (int p = 0; p < 3; p++) {
            const uint32_t aB = sb + aS[p] + aOffN, bB = sb + bS[p] + bOffT;
#pragma unroll
            for (int ks = 0; ks < 4; ks++) {
                uint32_t a[4];
                ldsm4(aB + ks * 32, a);
#pragma unroll
                for (int nb = 0; nb < 4; nb++) {
                    uint32_t b[4];
                    ldsm4t(bB + ks * 16 * PIT * 2 + nb * 32, b);
                    mma16816(accO[2 * nb],     a, b[0], b[1]);
                    mma16816(accO[2 * nb + 1], a, b[2], b[3]);
                }
            }
        }
    }

    // ---- O2 += P @ V (A = register P, B = V^T trans; causal k-blocks only) ----
    {
#pragma unroll
        for (int p = 0; p < 3; p++) {
            const uint32_t bB = sb + (p == 1 ? K3_VL : K3_VH) + bOffT;
#pragma unroll
            for (int kb = 0; kb < 4; kb++)
                if (kb <= w) {
                    const uint32_t (&a)[4] = (p < 2) ? aPh[kb] : aPl[kb];
#pragma unroll
                    for (int nb = 0; nb < 4; nb++) {
                        uint32_t b[4];
                        ldsm4t(bB + kb * 16 * PIT * 2 + nb * 32, b);
                        mma16816(accO[2 * nb],     a, b[0], b[1]);
                        mma16816(accO[2 * nb + 1], a, b[2], b[3]);
                    }
                }
        }
    }

    // ---- store O ----
    float* op = og + ((size_t)bh * TT + (size_t)c * CH) * DD;
#pragma unroll
    for (int nb8 = 0; nb8 < 8; nb8++) {
        const int e = 8 * nb8 + 2 * tig;
        *(float2*)(op + (size_t)i0 * DD + e)       = make_float2(accO[nb8][0], accO[nb8][1]);
        *(float2*)(op + (size_t)(i0 + 8) * DD + e) = make_float2(accO[nb8][2], accO[nb8][3]);
    }
}

// ---------------------------------------------------------------------------
extern "C" void kernel_launch(void* const* d_in, const int* in_sizes, int n_in,
                              void* d_out, int out_size) {
    const float* q = (const float*)d_in[0];
    const float* k = (const float*)d_in[1];
    const float* v = (const float*)d_in[2];
    float* o = (float*)d_out;

    cudaFuncSetAttribute(kv_kernel, cudaFuncAttributeMaxDynamicSharedMemorySize, K1_SMEM);
    cudaFuncSetAttribute(out_kernel, cudaFuncAttributeMaxDynamicSharedMemorySize, K3_SMEM);

    dim3 grid(NC, BH);
    kv_kernel<<<grid, 128, K1_SMEM>>>(k, v);
    prefix_kernel<<<dim3((DD * DD / 2) / 256, BH), 256>>>();
    out_kernel<<<grid, 128, K3_SMEM>>>(q, k, v, o);
}

// round 13
// speedup vs baseline: 1.1631x; 1.1631x over previous
#include <cuda_runtime.h>
#include <cuda_bf16.h>
#include <cstdint>

#define TT   2048
#define DD   64
#define CH   64
#define NC   (TT/CH)    // 32 chunks
#define BH   64         // B*H
#define PIT  72         // smem pitch in bf16 elements (144B rows, ldmatrix conflict-free)
#define TILE_B (DD*PIT*2)  // 9216 bytes per 64x64 bf16 tile

// Exclusive-prefix KV states, fp32: 64 * 32 * 64 * 64 * 4B = 32 MB
__device__ float g_state[(size_t)BH * NC * DD * DD];

// ---------------------------------------------------------------------------
// helpers
// ---------------------------------------------------------------------------
__device__ __forceinline__ uint32_t smem_u32(const void* p) {
    uint32_t a;
    asm("{ .reg .u64 t; cvta.to.shared.u64 t, %1; cvt.u32.u64 %0, t; }" : "=r"(a) : "l"(p));
    return a;
}
__device__ __forceinline__ void ldsm4(uint32_t addr, uint32_t r[4]) {
    asm volatile("ldmatrix.sync.aligned.m8n8.x4.shared.b16 {%0,%1,%2,%3}, [%4];"
                 : "=r"(r[0]), "=r"(r[1]), "=r"(r[2]), "=r"(r[3]) : "r"(addr));
}
__device__ __forceinline__ void ldsm4t(uint32_t addr, uint32_t r[4]) {
    asm volatile("ldmatrix.sync.aligned.m8n8.x4.trans.shared.b16 {%0,%1,%2,%3}, [%4];"
                 : "=r"(r[0]), "=r"(r[1]), "=r"(r[2]), "=r"(r[3]) : "r"(addr));
}
__device__ __forceinline__ void mma16816(float c[4], const uint32_t a[4], uint32_t b0, uint32_t b1) {
    asm volatile(
        "mma.sync.aligned.m16n8k16.row.col.f32.bf16.bf16.f32 "
        "{%0,%1,%2,%3}, {%4,%5,%6,%7}, {%8,%9}, {%0,%1,%2,%3};"
        : "+f"(c[0]), "+f"(c[1]), "+f"(c[2]), "+f"(c[3])
        : "r"(a[0]), "r"(a[1]), "r"(a[2]), "r"(a[3]), "r"(b0), "r"(b1));
}
// packed: d = {hi lane: bf16(hi), lo lane: bf16(lo)} (round-to-nearest, same as __float2bfloat16)
__device__ __forceinline__ uint32_t cvt_bf2(float hi, float lo) {
    uint32_t d;
    asm("cvt.rn.bf16x2.f32 %0, %1, %2;" : "=r"(d) : "f"(hi), "f"(lo));
    return d;
}
// split pair (x -> lo lane, y -> hi lane) into hi-plane and lo-plane words
__device__ __forceinline__ void split2(float x, float y, uint32_t& h, uint32_t& l) {
    h = cvt_bf2(y, x);
    float rx = x - __uint_as_float(h << 16);
    float ry = y - __uint_as_float(h & 0xFFFF0000u);
    l = cvt_bf2(ry, rx);
}
__device__ __forceinline__ void split4(float4 f, uint2& hi, uint2& lo) {
    split2(f.x, f.y, hi.x, lo.x);
    split2(f.z, f.w, hi.y, lo.y);
}

// ---------------------------------------------------------------------------
// Kernel 1: KV_c = K_c^T V_c. A = K^T via trans-ldmatrix of row-major K[j][d],
// B = V^T via trans-ldmatrix of row-major V[j][e]. Warp quadrants 32x32.
// ---------------------------------------------------------------------------
#define K1_KH 0
#define K1_KL (1*TILE_B)
#define K1_VH (2*TILE_B)
#define K1_VL (3*TILE_B)
#define K1_SMEM (4*TILE_B)

__global__ __launch_bounds__(128) void kv_kernel(const float* __restrict__ kg,
                                                 const float* __restrict__ vg) {
    extern __shared__ char sm[];
    const uint32_t sb = smem_u32(sm);
    const int tid = threadIdx.x, w = tid >> 5, l = tid & 31;
    const int c = blockIdx.x, bh = blockIdx.y;

    const float* kp = kg + ((size_t)bh * TT + (size_t)c * CH) * DD;
    const float* vp = vg + ((size_t)bh * TT + (size_t)c * CH) * DD;

#pragma unroll
    for (int it = 0; it < 8; it++) {
        int idx = tid + it * 128;
        int j = idx >> 4, d0 = (idx & 15) * 4;
        uint2 hi, lo;
        split4(*(const float4*)(kp + (size_t)j * DD + d0), hi, lo);
        *(uint2*)(sm + K1_KH + (j * PIT + d0) * 2) = hi;
        *(uint2*)(sm + K1_KL + (j * PIT + d0) * 2) = lo;
        split4(*(const float4*)(vp + (size_t)j * DD + d0), hi, lo);
        *(uint2*)(sm + K1_VH + (j * PIT + d0) * 2) = hi;
        *(uint2*)(sm + K1_VL + (j * PIT + d0) * 2) = lo;
    }
    __syncthreads();

    const int m0 = (w & 1) * 32, n0 = (w >> 1) * 32;
    const uint32_t aOff = (((l & 7) + ((l >> 4) & 1) * 8) * PIT + m0 + (l & 8)) * 2;
    const uint32_t bOff = (((l & 7) + (l & 8)) * PIT + n0 + ((l >> 4) & 1) * 8) * 2;

    float acc[2][4][4] = {};
    const uint32_t aSel[3] = {K1_KH, K1_KH, K1_KL};
    const uint32_t bSel[3] = {K1_VH, K1_VL, K1_VH};
#pragma unroll
    for (int p = 0; p < 3; p++) {
        const uint32_t aB = sb + aSel[p] + aOff, bB = sb + bSel[p] + bOff;
#pragma unroll
        for (int ks = 0; ks < 4; ks++) {
            const uint32_t ko = ks * 16 * PIT * 2;
            uint32_t a0[4], a1[4], b0[4], b1[4];
            ldsm4t(aB + ko, a0);
            ldsm4t(aB + ko + 32, a1);   // m0+16
            ldsm4t(bB + ko, b0);
            ldsm4t(bB + ko + 32, b1);   // n0+16
            mma16816(acc[0][0], a0, b0[0], b0[1]); mma16816(acc[0][1], a0, b0[2], b0[3]);
            mma16816(acc[0][2], a0, b1[0], b1[1]); mma16816(acc[0][3], a0, b1[2], b1[3]);
            mma16816(acc[1][0], a1, b0[0], b0[1]); mma16816(acc[1][1], a1, b0[2], b0[3]);
            mma16816(acc[1][2], a1, b1[0], b1[1]); mma16816(acc[1][3], a1, b1[2], b1[3]);
        }
    }

    float* outp = g_state + ((size_t)(bh * NC + c)) * (DD * DD);
#pragma unroll
    for (int mi = 0; mi < 2; mi++)
#pragma unroll
        for (int ni = 0; ni < 4; ni++)
#pragma unroll
            for (int half = 0; half < 2; half++) {
                int d = m0 + mi * 16 + (l >> 2) + half * 8;
                int e = n0 + ni * 8 + 2 * (l & 3);
                *(float2*)(outp + (size_t)d * DD + e) =
                    make_float2(acc[mi][ni][2 * half], acc[mi][ni][2 * half + 1]);
            }
}

// ---------------------------------------------------------------------------
// Kernel 2: exclusive prefix over 32 chunk states per bh (fp32, R4-exact)
// ---------------------------------------------------------------------------
__global__ __launch_bounds__(256) void prefix_kernel() {
    const int e = blockIdx.x * 256 + threadIdx.x;
    const int bh = blockIdx.y;
    size_t base = (size_t)bh * NC * (DD * DD) + e;
    float run = 0.f;
#pragma unroll
    for (int c = 0; c < NC; c++) {
        float t = g_state[base + (size_t)c * (DD * DD)];
        g_state[base + (size_t)c * (DD * DD)] = run;
        run += t;
    }
}

// ---------------------------------------------------------------------------
// Kernel 3 (R4-exact structure): P = tril(Q K^T); O = Q S + P V.
// Row-stripe warps (16 rows each), P in registers, causal MMA skipping.
// ---------------------------------------------------------------------------
#define K3_QH 0
#define K3_QL (1*TILE_B)
#define K3_KH (2*TILE_B)
#define K3_KL (3*TILE_B)
#define K3_VH (4*TILE_B)
#define K3_VL (5*TILE_B)
#define K3_SH (6*TILE_B)
#define K3_SL (7*TILE_B)
#define K3_SMEM (8*TILE_B)

__global__ __launch_bounds__(128) void out_kernel(const float* __restrict__ qg,
                                                  const float* __restrict__ kg,
                                                  const float* __restrict__ vg,
                                                  float* __restrict__ og) {
    extern __shared__ char sm[];
    const uint32_t sb = smem_u32(sm);
    const int tid = threadIdx.x, w = tid >> 5, l = tid & 31;
    const int c = blockIdx.x, bh = blockIdx.y;

    const float* qp = qg + ((size_t)bh * TT + (size_t)c * CH) * DD;
    const float* kp = kg + ((size_t)bh * TT + (size_t)c * CH) * DD;
    const float* vp = vg + ((size_t)bh * TT + (size_t)c * CH) * DD;
    const float* sp = g_state + ((size_t)(bh * NC + c)) * (DD * DD);

#pragma unroll
    for (int it = 0; it < 8; it++) {
        int idx = tid + it * 128;
        int r = idx >> 4, d0 = (idx & 15) * 4;
        const uint32_t so = (r * PIT + d0) * 2;
        uint2 hi, lo;
        split4(*(const float4*)(qp + (size_t)r * DD + d0), hi, lo);
        *(uint2*)(sm + K3_QH + so) = hi;  *(uint2*)(sm + K3_QL + so) = lo;
        split4(*(const float4*)(kp + (size_t)r * DD + d0), hi, lo);
        *(uint2*)(sm + K3_KH + so) = hi;  *(uint2*)(sm + K3_KL + so) = lo;
        split4(*(const float4*)(vp + (size_t)r * DD + d0), hi, lo);
        *(uint2*)(sm + K3_VH + so) = hi;  *(uint2*)(sm + K3_VL + so) = lo;
        split4(*(const float4*)(sp + (size_t)r * DD + d0), hi, lo);
        *(uint2*)(sm + K3_SH + so) = hi;  *(uint2*)(sm + K3_SL + so) = lo;
    }
    __syncthreads();

    const int m0 = w * 16;
    const int gid = l >> 2, tig = l & 3;
    const int i0 = m0 + gid;
    const uint32_t aOffN = ((m0 + (l & 15)) * PIT + ((l >> 4) << 3)) * 2;
    const uint32_t bOffN = (((l & 7) + ((l & 16) >> 1)) * PIT + ((l >> 3) & 1) * 8) * 2;
    const uint32_t bOffT = (((l & 7) + (l & 8)) * PIT + ((l >> 4) & 1) * 8) * 2;

    // ---- P = Q K^T (causal: only n-blocks j <= 16(w+1)) ----
    float accP[8][4] = {};
    {
        const uint32_t aS[3] = {K3_QH, K3_QH, K3_QL};
        const uint32_t bS[3] = {K3_KH, K3_KL, K3_KH};
#pragma unroll
        for (int p = 0; p < 3; p++) {
            const uint32_t aB = sb + aS[p] + aOffN, bB = sb + bS[p] + bOffN;
#pragma unroll
            for (int ks = 0; ks < 4; ks++) {
                uint32_t a[4];
                ldsm4(aB + ks * 32, a);
#pragma unroll
                for (int nb = 0; nb < 4; nb++)
                    if (nb <= w) {
                        uint32_t b[4];
                        ldsm4(bB + nb * 16 * PIT * 2 + ks * 32, b);
                        mma16816(accP[2 * nb],     a, b[0], b[1]);
                        mma16816(accP[2 * nb + 1], a, b[2], b[3]);
                    }
            }
        }
    }

    // ---- mask + in-register split to A-operand fragments (packed cvt) ----
    uint32_t aPh[4][4], aPl[4][4];
#pragma unroll
    for (int nb = 0; nb < 4; nb++)
        if (nb <= w) {
#pragma unroll
            for (int s2 = 0; s2 < 2; s2++) {
                const int j0 = 16 * nb + 8 * s2 + 2 * tig;
                float c0 = (j0     <= i0)     ? accP[2 * nb + s2][0] : 0.f;
                float c1 = (j0 + 1 <= i0)     ? accP[2 * nb + s2][1] : 0.f;
                float c2 = (j0     <= i0 + 8) ? accP[2 * nb + s2][2] : 0.f;
                float c3 = (j0 + 1 <= i0 + 8) ? accP[2 * nb + s2][3] : 0.f;
                split2(c0, c1, aPh[nb][2 * s2],     aPl[nb][2 * s2]);
                split2(c2, c3, aPh[nb][2 * s2 + 1], aPl[nb][2 * s2 + 1]);
            }
        }

    // ---- O1 = Q @ S (B = S^T via trans loads of S[d][e]) ----
    float accO[8][4] = {};
    {
        const uint32_t aS[3] = {K3_QH, K3_QH, K3_QL};
        const uint32_t bS[3] = {K3_SH, K3_SL, K3_SH};
#pragma unroll
        for (int p = 0; p < 3; p++) {
            const uint32_t aB = sb + aS[p] + aOffN, bB = sb + bS[p] + bOffT;
#pragma unroll
            for (int ks = 0; ks < 4; ks++) {
                uint32_t a[4];
                ldsm4(aB + ks * 32, a);
#pragma unroll
                for (int nb = 0; nb < 4; nb++) {
                    uint32_t b[4];
                    ldsm4t(bB + ks * 16 * PIT * 2 + nb * 32, b);
                    mma16816(accO[2 * nb],     a, b[0], b[1]);
                    mma16816(accO[2 * nb + 1], a, b[2], b[3]);
                }
            }
        }
    }

    // ---- O2 += P @ V (A = register P, B = V^T trans; causal k-blocks only) ----
    {
#pragma unroll
        for (int p = 0; p < 3; p++) {
            const uint32_t bB = sb + (p == 1 ? K3_VL : K3_VH) + bOffT;
#pragma unroll
            for (int kb = 0; kb < 4; kb++)
                if (kb <= w) {
                    const uint32_t (&a)[4] = (p < 2) ? aPh[kb] : aPl[kb];
#pragma unroll
                    for (int nb = 0; nb < 4; nb++) {
                        uint32_t b[4];
                        ldsm4t(bB + kb * 16 * PIT * 2 + nb * 32, b);
                        mma16816(accO[2 * nb],     a, b[0], b[1]);
                        mma16816(accO[2 * nb + 1], a, b[2], b[3]);
                    }
                }
        }
    }

    // ---- store O ----
    float* op = og + ((size_t)bh * TT + (size_t)c * CH) * DD;
#pragma unroll
    for (int nb8 = 0; nb8 < 8; nb8++) {
        const int e = 8 * nb8 + 2 * tig;
        *(float2*)(op + (size_t)i0 * DD + e)       = make_float2(accO[nb8][0], accO[nb8][1]);
        *(float2*)(op + (size_t)(i0 + 8) * DD + e) = make_float2(accO[nb8][2], accO[nb8][3]);
    }
}

// ---------------------------------------------------------------------------
extern "C" void kernel_launch(void* const* d_in, const int* in_sizes, int n_in,
                              void* d_out, int out_size) {
    const float* q = (const float*)d_in[0];
    const float* k = (const float*)d_in[1];
    const float* v = (const float*)d_in[2];
    float* o = (float*)d_out;

    cudaFuncSetAttribute(kv_kernel, cudaFuncAttributeMaxDynamicSharedMemorySize, K1_SMEM);
    cudaFuncSetAttribute(out_kernel, cudaFuncAttributeMaxDynamicSharedMemorySize, K3_SMEM);

    dim3 grid(NC, BH);
    kv_kernel<<<grid, 128, K1_SMEM>>>(k, v);
    prefix_kernel<<<dim3((DD * DD) / 256, BH), 256>>>();
    out_kernel<<<grid, 128, K3_SMEM>>>(q, k, v, o);
}

// round 14
// speedup vs baseline: 1.2227x; 1.0513x over previous
#include <cuda_runtime.h>
#include <cuda_bf16.h>
#include <cstdint>

#define TT   2048
#define DD   64
#define CH   64
#define NC   (TT/CH)    // 32 chunks
#define BH   64         // B*H
#define PIT  72         // smem pitch in bf16 elements (144B rows, ldmatrix conflict-free)
#define TILE_B (DD*PIT*2)  // 9216 bytes per 64x64 bf16 tile

// Exclusive-prefix KV states, fp32: 32 MB
__device__ float g_state[(size_t)BH * NC * DD * DD];

// ---------------------------------------------------------------------------
// helpers
// ---------------------------------------------------------------------------
__device__ __forceinline__ uint32_t smem_u32(const void* p) {
    uint32_t a;
    asm("{ .reg .u64 t; cvta.to.shared.u64 t, %1; cvt.u32.u64 %0, t; }" : "=r"(a) : "l"(p));
    return a;
}
__device__ __forceinline__ void ldsm4(uint32_t addr, uint32_t r[4]) {
    asm volatile("ldmatrix.sync.aligned.m8n8.x4.shared.b16 {%0,%1,%2,%3}, [%4];"
                 : "=r"(r[0]), "=r"(r[1]), "=r"(r[2]), "=r"(r[3]) : "r"(addr));
}
__device__ __forceinline__ void ldsm4t(uint32_t addr, uint32_t r[4]) {
    asm volatile("ldmatrix.sync.aligned.m8n8.x4.trans.shared.b16 {%0,%1,%2,%3}, [%4];"
                 : "=r"(r[0]), "=r"(r[1]), "=r"(r[2]), "=r"(r[3]) : "r"(addr));
}
__device__ __forceinline__ void mma16816(float c[4], const uint32_t a[4], uint32_t b0, uint32_t b1) {
    asm volatile(
        "mma.sync.aligned.m16n8k16.row.col.f32.bf16.bf16.f32 "
        "{%0,%1,%2,%3}, {%4,%5,%6,%7}, {%8,%9}, {%0,%1,%2,%3};"
        : "+f"(c[0]), "+f"(c[1]), "+f"(c[2]), "+f"(c[3])
        : "r"(a[0]), "r"(a[1]), "r"(a[2]), "r"(a[3]), "r"(b0), "r"(b1));
}
__device__ __forceinline__ uint32_t cvt_bf2(float hi, float lo) {
    uint32_t d;
    asm("cvt.rn.bf16x2.f32 %0, %1, %2;" : "=r"(d) : "f"(hi), "f"(lo));
    return d;
}
__device__ __forceinline__ void split2(float x, float y, uint32_t& h, uint32_t& l) {
    h = cvt_bf2(y, x);
    float rx = x - __uint_as_float(h << 16);
    float ry = y - __uint_as_float(h & 0xFFFF0000u);
    l = cvt_bf2(ry, rx);
}
__device__ __forceinline__ void split4(float4 f, uint2& hi, uint2& lo) {
    split2(f.x, f.y, hi.x, lo.x);
    split2(f.z, f.w, hi.y, lo.y);
}

// ---------------------------------------------------------------------------
// Kernel 1: KV_c = K_c^T V_c (R13-exact; kv best = 19.8us)
// ---------------------------------------------------------------------------
#define K1_KH 0
#define K1_KL (1*TILE_B)
#define K1_VH (2*TILE_B)
#define K1_VL (3*TILE_B)
#define K1_SMEM (4*TILE_B)

__global__ __launch_bounds__(128) void kv_kernel(const float* __restrict__ kg,
                                                 const float* __restrict__ vg) {
    extern __shared__ char sm[];
    const uint32_t sb = smem_u32(sm);
    const int tid = threadIdx.x, w = tid >> 5, l = tid & 31;
    const int c = blockIdx.x, bh = blockIdx.y;

    const float* kp = kg + ((size_t)bh * TT + (size_t)c * CH) * DD;
    const float* vp = vg + ((size_t)bh * TT + (size_t)c * CH) * DD;

#pragma unroll
    for (int it = 0; it < 8; it++) {
        int idx = tid + it * 128;
        int j = idx >> 4, d0 = (idx & 15) * 4;
        uint2 hi, lo;
        split4(*(const float4*)(kp + (size_t)j * DD + d0), hi, lo);
        *(uint2*)(sm + K1_KH + (j * PIT + d0) * 2) = hi;
        *(uint2*)(sm + K1_KL + (j * PIT + d0) * 2) = lo;
        split4(*(const float4*)(vp + (size_t)j * DD + d0), hi, lo);
        *(uint2*)(sm + K1_VH + (j * PIT + d0) * 2) = hi;
        *(uint2*)(sm + K1_VL + (j * PIT + d0) * 2) = lo;
    }
    __syncthreads();

    const int m0 = (w & 1) * 32, n0 = (w >> 1) * 32;
    const uint32_t aOff = (((l & 7) + ((l >> 4) & 1) * 8) * PIT + m0 + (l & 8)) * 2;
    const uint32_t bOff = (((l & 7) + (l & 8)) * PIT + n0 + ((l >> 4) & 1) * 8) * 2;

    float acc[2][4][4] = {};
    const uint32_t aSel[3] = {K1_KH, K1_KH, K1_KL};
    const uint32_t bSel[3] = {K1_VH, K1_VL, K1_VH};
#pragma unroll
    for (int p = 0; p < 3; p++) {
        const uint32_t aB = sb + aSel[p] + aOff, bB = sb + bSel[p] + bOff;
#pragma unroll
        for (int ks = 0; ks < 4; ks++) {
            const uint32_t ko = ks * 16 * PIT * 2;
            uint32_t a0[4], a1[4], b0[4], b1[4];
            ldsm4t(aB + ko, a0);
            ldsm4t(aB + ko + 32, a1);
            ldsm4t(bB + ko, b0);
            ldsm4t(bB + ko + 32, b1);
            mma16816(acc[0][0], a0, b0[0], b0[1]); mma16816(acc[0][1], a0, b0[2], b0[3]);
            mma16816(acc[0][2], a0, b1[0], b1[1]); mma16816(acc[0][3], a0, b1[2], b1[3]);
            mma16816(acc[1][0], a1, b0[0], b0[1]); mma16816(acc[1][1], a1, b0[2], b0[3]);
            mma16816(acc[1][2], a1, b1[0], b1[1]); mma16816(acc[1][3], a1, b1[2], b1[3]);
        }
    }

    float* outp = g_state + ((size_t)(bh * NC + c)) * (DD * DD);
#pragma unroll
    for (int mi = 0; mi < 2; mi++)
#pragma unroll
        for (int ni = 0; ni < 4; ni++)
#pragma unroll
            for (int half = 0; half < 2; half++) {
                int d = m0 + mi * 16 + (l >> 2) + half * 8;
                int e = n0 + ni * 8 + 2 * (l & 3);
                *(float2*)(outp + (size_t)d * DD + e) =
                    make_float2(acc[mi][ni][2 * half], acc[mi][ni][2 * half + 1]);
            }
}

// ---------------------------------------------------------------------------
// Kernel 2: exclusive prefix (R13-exact)
// ---------------------------------------------------------------------------
__global__ __launch_bounds__(256) void prefix_kernel() {
    const int e = blockIdx.x * 256 + threadIdx.x;
    const int bh = blockIdx.y;
    size_t base = (size_t)bh * NC * (DD * DD) + e;
    float run = 0.f;
#pragma unroll
    for (int c = 0; c < NC; c++) {
        float t = g_state[base + (size_t)c * (DD * DD)];
        g_state[base + (size_t)c * (DD * DD)] = run;
        run += t;
    }
}

// ---------------------------------------------------------------------------
// Kernel 3: 8-warp (256-thread) out. Warp (r,h): rows 16r, n-half 32h.
// P quarter computed per warp -> masked/split -> smem P tiles -> O2 reads back.
// ---------------------------------------------------------------------------
#define K3_QH 0
#define K3_QL (1*TILE_B)
#define K3_KH (2*TILE_B)
#define K3_KL (3*TILE_B)
#define K3_VH (4*TILE_B)
#define K3_VL (5*TILE_B)
#define K3_SH (6*TILE_B)
#define K3_SL (7*TILE_B)
#define K3_PH (8*TILE_B)
#define K3_PL (9*TILE_B)
#define K3_SMEM (10*TILE_B)   // 92160 B

__global__ __launch_bounds__(256) void out_kernel(const float* __restrict__ qg,
                                                  const float* __restrict__ kg,
                                                  const float* __restrict__ vg,
                                                  float* __restrict__ og) {
    extern __shared__ char sm[];
    const uint32_t sb = smem_u32(sm);
    const int tid = threadIdx.x, w = tid >> 5, l = tid & 31;
    const int c = blockIdx.x, bh = blockIdx.y;

    const float* qp = qg + ((size_t)bh * TT + (size_t)c * CH) * DD;
    const float* kp = kg + ((size_t)bh * TT + (size_t)c * CH) * DD;
    const float* vp = vg + ((size_t)bh * TT + (size_t)c * CH) * DD;
    const float* sp = g_state + ((size_t)(bh * NC + c)) * (DD * DD);

#pragma unroll
    for (int it = 0; it < 4; it++) {
        int idx = tid + it * 256;
        int r_ = idx >> 4, d0 = (idx & 15) * 4;
        const uint32_t so = (r_ * PIT + d0) * 2;
        uint2 hi, lo;
        split4(*(const float4*)(qp + (size_t)r_ * DD + d0), hi, lo);
        *(uint2*)(sm + K3_QH + so) = hi;  *(uint2*)(sm + K3_QL + so) = lo;
        split4(*(const float4*)(kp + (size_t)r_ * DD + d0), hi, lo);
        *(uint2*)(sm + K3_KH + so) = hi;  *(uint2*)(sm + K3_KL + so) = lo;
        split4(*(const float4*)(vp + (size_t)r_ * DD + d0), hi, lo);
        *(uint2*)(sm + K3_VH + so) = hi;  *(uint2*)(sm + K3_VL + so) = lo;
        split4(*(const float4*)(sp + (size_t)r_ * DD + d0), hi, lo);
        *(uint2*)(sm + K3_SH + so) = hi;  *(uint2*)(sm + K3_SL + so) = lo;
    }
    __syncthreads();

    const int r = w & 3;       // row block: rows 16r..16r+15
    const int h = w >> 2;      // n-half: cols 32h..32h+31
    const int m0 = r * 16;
    const int gid = l >> 2, tig = l & 3;
    const int i0 = m0 + gid;
    const uint32_t aOffN = ((m0 + (l & 15)) * PIT + ((l >> 4) << 3)) * 2;
    const uint32_t bOffN = (((l & 7) + ((l & 16) >> 1)) * PIT + ((l >> 3) & 1) * 8) * 2;
    const uint32_t bOffT = (((l & 7) + (l & 8)) * PIT + ((l >> 4) & 1) * 8) * 2;

    // ---- P quarter: rows 16r x cols [32h, 32h+32), causal nb <= r ----
    float accP[4][4] = {};
    {
        const uint32_t aS[3] = {K3_QH, K3_QH, K3_QL};
        const uint32_t bS[3] = {K3_KH, K3_KL, K3_KH};
#pragma unroll
        for (int p = 0; p < 3; p++) {
            const uint32_t aB = sb + aS[p] + aOffN, bB = sb + bS[p] + bOffN;
#pragma unroll
            for (int ks = 0; ks < 4; ks++) {
                uint32_t a[4];
                ldsm4(aB + ks * 32, a);
#pragma unroll
                for (int nbL = 0; nbL < 2; nbL++) {
                    const int nb = 2 * h + nbL;
                    if (nb <= r) {
                        uint32_t b[4];
                        ldsm4(bB + nb * 16 * PIT * 2 + ks * 32, b);
                        mma16816(accP[2 * nbL],     a, b[0], b[1]);
                        mma16816(accP[2 * nbL + 1], a, b[2], b[3]);
                    }
                }
            }
        }
    }

    // ---- mask + split + store P quarter to smem planes ----
#pragma unroll
    for (int nbL = 0; nbL < 2; nbL++) {
        const int nb = 2 * h + nbL;
        if (nb <= r) {
#pragma unroll
            for (int s2 = 0; s2 < 2; s2++) {
                const int j0 = 16 * nb + 8 * s2 + 2 * tig;
                float c0 = (j0     <= i0)     ? accP[2 * nbL + s2][0] : 0.f;
                float c1 = (j0 + 1 <= i0)     ? accP[2 * nbL + s2][1] : 0.f;
                float c2 = (j0     <= i0 + 8) ? accP[2 * nbL + s2][2] : 0.f;
                float c3 = (j0 + 1 <= i0 + 8) ? accP[2 * nbL + s2][3] : 0.f;
                uint32_t hw, lw;
                split2(c0, c1, hw, lw);
                *(uint32_t*)(sm + K3_PH + (i0 * PIT + j0) * 2) = hw;
                *(uint32_t*)(sm + K3_PL + (i0 * PIT + j0) * 2) = lw;
                split2(c2, c3, hw, lw);
                *(uint32_t*)(sm + K3_PH + ((i0 + 8) * PIT + j0) * 2) = hw;
                *(uint32_t*)(sm + K3_PL + ((i0 + 8) * PIT + j0) * 2) = lw;
            }
        }
    }
    __syncthreads();

    // ---- O1 = Q @ S for e-half h ----
    float accO[4][4] = {};
    {
        const uint32_t aS[3] = {K3_QH, K3_QH, K3_QL};
        const uint32_t bS[3] = {K3_SH, K3_SL, K3_SH};
#pragma unroll
        for (int p = 0; p < 3; p++) {
            const uint32_t aB = sb + aS[p] + aOffN, bB = sb + bS[p] + bOffT;
#pragma unroll
            for (int ks = 0; ks < 4; ks++) {
                uint32_t a[4];
                ldsm4(aB + ks * 32, a);
#pragma unroll
                for (int nbL = 0; nbL < 2; nbL++) {
                    const int nbE = 2 * h + nbL;
                    uint32_t b[4];
                    ldsm4t(bB + ks * 16 * PIT * 2 + nbE * 32, b);
                    mma16816(accO[2 * nbL],     a, b[0], b[1]);
                    mma16816(accO[2 * nbL + 1], a, b[2], b[3]);
                }
            }
        }
    }

    // ---- O2 += P @ V (A = P from smem, kb <= r; B = V^T trans, e-half h) ----
    {
        const uint32_t aOffP = aOffN;   // same row-major A addressing
#pragma unroll
        for (int p = 0; p < 3; p++) {
            const uint32_t aB = sb + (p == 2 ? K3_PL : K3_PH) + aOffP;
            const uint32_t bB = sb + (p == 1 ? K3_VL : K3_VH) + bOffT;
#pragma unroll
            for (int kb = 0; kb < 4; kb++)
                if (kb <= r) {
                    uint32_t a[4];
                    ldsm4(aB + kb * 32, a);
#pragma unroll
                    for (int nbL = 0; nbL < 2; nbL++) {
                        const int nbE = 2 * h + nbL;
                        uint32_t b[4];
                        ldsm4t(bB + kb * 16 * PIT * 2 + nbE * 32, b);
                        mma16816(accO[2 * nbL],     a, b[0], b[1]);
                        mma16816(accO[2 * nbL + 1], a, b[2], b[3]);
                    }
                }
        }
    }

    // ---- store O (rows i0, i0+8; cols 32h + 8*nb8 + 2*tig) ----
    float* op = og + ((size_t)bh * TT + (size_t)c * CH) * DD;
#pragma unroll
    for (int nb8 = 0; nb8 < 4; nb8++) {
        const int e = 32 * h + 8 * nb8 + 2 * tig;
        *(float2*)(op + (size_t)i0 * DD + e)       = make_float2(accO[nb8][0], accO[nb8][1]);
        *(float2*)(op + (size_t)(i0 + 8) * DD + e) = make_float2(accO[nb8][2], accO[nb8][3]);
    }
}

// ---------------------------------------------------------------------------
extern "C" void kernel_launch(void* const* d_in, const int* in_sizes, int n_in,
                              void* d_out, int out_size) {
    const float* q = (const float*)d_in[0];
    const float* k = (const float*)d_in[1];
    const float* v = (const float*)d_in[2];
    float* o = (float*)d_out;

    cudaFuncSetAttribute(kv_kernel, cudaFuncAttributeMaxDynamicSharedMemorySize, K1_SMEM);
    cudaFuncSetAttribute(out_kernel, cudaFuncAttributeMaxDynamicSharedMemorySize, K3_SMEM);

    dim3 grid(NC, BH);
    kv_kernel<<<grid, 128, K1_SMEM>>>(k, v);
    prefix_kernel<<<dim3((DD * DD) / 256, BH), 256>>>();
    out_kernel<<<grid, 256, K3_SMEM>>>(q, k, v, o);
}